// round 10
// baseline (speedup 1.0000x reference)
#include <cuda_runtime.h>
#include <cstdint>

// Shapes: N=128, T=256, E=6, D=10
//   y_pred_i : (128,256,6)   fp32
//   y_pred_ij: (128,128,256,6) fp32  (~100.7 MB, streamed once via cp.async.bulk)
//   input1   : (128,256,15)  fp32  (err_true = cols 7..12)
//   samples  : (128,10)      fp32
// Output: scalar fp32 L_sim.

#define NPAIR 128
#define TE 1536                 // T*E
#define ROW_BYTES 6144          // TE * 4
#define NBUF 16                 // ring depth (2 buffers per consumer warp)
#define NBLOCKS 256             // 128 j * 2 halves

// smem layout (bytes, dynamic):
#define SM_W    0                       // w tile      (6144)
#define SM_Y    6144                    // y_pred_i[j] (6144)
#define SM_BUF  12288                   // 16 row buffers (98304)
#define SM_MBAR (12288 + 98304)         // full[16] @ +0, empty[16] @ +128
#define SMEM_TOTAL (SM_MBAR + 256)      // 110848

__device__ float    g_second [NPAIR * NPAIR];
__device__ float    g_secondT[NPAIR * NPAIR];
__device__ unsigned g_ctr = 0;

// ---- minimal PTX wrappers ---------------------------------------------------
__device__ __forceinline__ uint32_t smem_u32(const void* p) {
    return (uint32_t)__cvta_generic_to_shared(p);
}
__device__ __forceinline__ void mbar_init(uint32_t a, uint32_t cnt) {
    asm volatile("mbarrier.init.shared.b64 [%0], %1;" :: "r"(a), "r"(cnt) : "memory");
}
__device__ __forceinline__ void mbar_expect_tx(uint32_t a, uint32_t bytes) {
    asm volatile("mbarrier.arrive.expect_tx.shared.b64 _, [%0], %1;"
                 :: "r"(a), "r"(bytes) : "memory");
}
__device__ __forceinline__ void mbar_arrive(uint32_t a) {
    asm volatile("mbarrier.arrive.shared.b64 _, [%0];" :: "r"(a) : "memory");
}
__device__ __forceinline__ void mbar_wait(uint32_t a, uint32_t parity) {
    asm volatile(
        "{\n\t.reg .pred P;\n\t"
        "W_%=:\n\t"
        "mbarrier.try_wait.parity.acquire.cta.shared::cta.b64 P, [%0], %1, 0x989680;\n\t"
        "@P bra D_%=;\n\t"
        "bra W_%=;\n\t"
        "D_%=:\n\t}"
        :: "r"(a), "r"(parity) : "memory");
}
__device__ __forceinline__ void bulk_copy_g2s(uint32_t dst, const void* src,
                                              uint32_t bytes, uint32_t mbar) {
    asm volatile(
        "cp.async.bulk.shared::cluster.global.mbarrier::complete_tx::bytes "
        "[%0], [%1], %2, [%3];"
        :: "r"(dst), "l"(src), "r"(bytes), "r"(mbar) : "memory");
}
// Named barrier among the 8 consumer warps only (threads 0-255).
__device__ __forceinline__ void consumer_bar() {
    asm volatile("bar.sync 1, 256;" ::: "memory");
}

// ---------------------------------------------------------------------------
// Single persistent kernel.
// grid = (j:128, half:2) = 256 blocks (single wave @ 2 blocks/SM).
// block = 288 threads: warps 0-7 consume, warp 8 produces (TMA).
// Phase 1: second[i,j] = sum_{t,e}(yij-yi)^2 / err^2 / 15360 (bulk-async
//          pipeline, proven R9). Producer starts BEFORE w/y staging.
// Phase 2: last block (ticket) computes the full L_sim with 256 threads.
// ---------------------------------------------------------------------------
__global__ void __launch_bounds__(288)
fused_kernel(const float* __restrict__ yij,
             const float* __restrict__ yi,
             const float* __restrict__ in1,
             const float* __restrict__ samples,
             float* __restrict__ out)
{
    extern __shared__ __align__(128) unsigned char smem[];
    float* w_f = reinterpret_cast<float*>(smem + SM_W);
    float* y_f = reinterpret_cast<float*>(smem + SM_Y);
    const uint32_t sbase      = smem_u32(smem);
    const uint32_t mbar_full  = sbase + SM_MBAR;         // + 8*b
    const uint32_t mbar_empty = sbase + SM_MBAR + 128;   // + 8*b

    const int j    = blockIdx.x;
    const int half = blockIdx.y;
    const int tid  = threadIdx.x;
    const int warp = tid >> 5;
    const int lane = tid & 31;

    if (tid < NBUF) {
        mbar_init(mbar_full  + tid * 8, 1);
        mbar_init(mbar_empty + tid * 8, 1);
    }
    __syncthreads();   // mbarriers visible; producer launches immediately

    if (warp == 8) {
        // ---- producer: one elected lane issues 64 bulk copies ---------------
        if (lane == 0) {
            for (int r = 0; r < 64; ++r) {
                const int b = r & 15;
                const int k = r >> 4;
                if (k > 0) mbar_wait(mbar_empty + b * 8, (unsigned)((k - 1) & 1));
                mbar_expect_tx(mbar_full + b * 8, ROW_BYTES);
                const float* src =
                    yij + (size_t)((half * 64 + r) * NPAIR + j) * TE;
                bulk_copy_g2s(sbase + SM_BUF + b * ROW_BYTES, src,
                              ROW_BYTES, mbar_full + b * 8);
            }
        }
        return;   // producer warp exits; consumers use named barrier only
    }

    // ---- consumers stage w/y while the first TMA copies are in flight ------
    const float scale = 1.0f / 15360.0f;   // 1/(T*E*10)
    for (int idx = tid; idx < TE; idx += 256) {
        int t = idx / 6;
        int c = idx - t * 6;
        float e = in1[(j * 256 + t) * 15 + 7 + c];
        w_f[idx] = scale / (e * e);
        y_f[idx] = yi[j * TE + idx];
    }
    consumer_bar();

    // ---- consumer warp w owns buffers 2w, 2w+1 ------------------------------
    const int b0 = 2 * warp;
    const int b1 = 2 * warp + 1;
    const float4* w4   = reinterpret_cast<const float4*>(w_f);
    const float4* y4   = reinterpret_cast<const float4*>(y_f);
    const float4* buf0 = reinterpret_cast<const float4*>(smem + SM_BUF + b0 * ROW_BYTES);
    const float4* buf1 = reinterpret_cast<const float4*>(smem + SM_BUF + b1 * ROW_BYTES);

    for (int k = 0; k < 4; ++k) {
        mbar_wait(mbar_full + b0 * 8, (unsigned)(k & 1));
        mbar_wait(mbar_full + b1 * 8, (unsigned)(k & 1));

        float a0 = 0.0f, a1 = 0.0f;
        #pragma unroll
        for (int q = 0; q < 12; ++q) {
            const int x = lane + 32 * q;
            const float4 wv = w4[x];
            const float4 yv = y4[x];
            const float4 g0 = buf0[x];
            const float4 g1 = buf1[x];
            float d;
            d = g0.x - yv.x; a0 = fmaf(d * d, wv.x, a0);
            d = g0.y - yv.y; a0 = fmaf(d * d, wv.y, a0);
            d = g0.z - yv.z; a0 = fmaf(d * d, wv.z, a0);
            d = g0.w - yv.w; a0 = fmaf(d * d, wv.w, a0);
            d = g1.x - yv.x; a1 = fmaf(d * d, wv.x, a1);
            d = g1.y - yv.y; a1 = fmaf(d * d, wv.y, a1);
            d = g1.z - yv.z; a1 = fmaf(d * d, wv.z, a1);
            d = g1.w - yv.w; a1 = fmaf(d * d, wv.w, a1);
        }
        #pragma unroll
        for (int o = 16; o; o >>= 1) {
            a0 += __shfl_xor_sync(0xFFFFFFFFu, a0, o);
            a1 += __shfl_xor_sync(0xFFFFFFFFu, a1, o);
        }
        __syncwarp();          // all lanes done reading the buffers
        if (lane == 0) {
            const int i0 = half * 64 + k * 16 + 2 * warp;
            g_second [i0 * NPAIR + j]       = a0;
            g_second [(i0 + 1) * NPAIR + j] = a1;
            g_secondT[j * NPAIR + i0]       = a0;
            g_secondT[j * NPAIR + i0 + 1]   = a1;
            mbar_arrive(mbar_empty + b0 * 8);   // release buffers
            mbar_arrive(mbar_empty + b1 * 8);
        }
    }

    // ---- ticket: last finished block computes the final loss ---------------
    if (lane == 0) __threadfence();   // storing lanes publish their results
    consumer_bar();                   // fences complete before the ticket

    __shared__ unsigned s_ticket;
    __shared__ float    s_part[8];
    if (tid == 0) s_ticket = atomicAdd(&g_ctr, 1u);
    consumer_bar();
    if (s_ticket != NBLOCKS - 1) return;

    if (tid == 0) g_ctr = 0;          // reset for the next graph replay

    // Stage samples (1280 floats) into the (now free) buffer region.
    float* smp = reinterpret_cast<float*>(smem + SM_BUF);
    for (int x = tid; x < 1280; x += 256) smp[x] = samples[x];
    consumer_bar();

    const int jj = tid & 127;
    const int h  = tid >> 7;
    float sj[10];
    #pragma unroll
    for (int d = 0; d < 10; ++d) sj[d] = smp[jj * 10 + d];

    float acc = 0.0f;
    const int ibeg = h * 64;
    #pragma unroll 8
    for (int q = 0; q < 64; ++q) {
        const int i = ibeg + q;
        float S = 0.0f;
        #pragma unroll
        for (int d = 0; d < 10; ++d) {
            float df = smp[i * 10 + d] - sj[d];
            S = fmaf(df, df, S);
        }
        float sA = __ldcg(&g_second [i * NPAIR + jj]);   // coalesced
        float sB = __ldcg(&g_secondT[i * NPAIR + jj]);   // coalesced
        acc += fabsf(S * 0.1f - 0.5f * (sA + sB));
    }
    #pragma unroll
    for (int o = 16; o; o >>= 1)
        acc += __shfl_xor_sync(0xFFFFFFFFu, acc, o);
    if (lane == 0) s_part[warp] = acc;
    consumer_bar();

    if (tid == 0) {
        float s = 0.0f;
        #pragma unroll
        for (int w = 0; w < 8; ++w) s += s_part[w];
        out[0] = s * (1.0f / 16384.0f);
    }
}

// ---------------------------------------------------------------------------
extern "C" void kernel_launch(void* const* d_in, const int* in_sizes, int n_in,
                              void* d_out, int out_size)
{
    (void)in_sizes; (void)n_in; (void)out_size;
    const float* yi      = (const float*)d_in[1];
    const float* yij     = (const float*)d_in[2];
    const float* in1     = (const float*)d_in[3];
    const float* samples = (const float*)d_in[4];
    float* out = (float*)d_out;

    static int smem_set = 0;
    if (!smem_set) {
        cudaFuncSetAttribute(fused_kernel,
                             cudaFuncAttributeMaxDynamicSharedMemorySize,
                             SMEM_TOTAL);
        smem_set = 1;
    }

    dim3 grid(NPAIR, 2);   // 256 blocks -> single wave at 2 blocks/SM
    fused_kernel<<<grid, 288, SMEM_TOTAL>>>(yij, yi, in1, samples, out);
}

// round 11
// speedup vs baseline: 1.3516x; 1.3516x over previous
#include <cuda_runtime.h>
#include <cstdint>

// Shapes: N=128, T=256, E=6, D=10
//   y_pred_i : (128,256,6)   fp32
//   y_pred_ij: (128,128,256,6) fp32  (~100.7 MB, streamed once via cp.async.bulk)
//   input1   : (128,256,15)  fp32  (err_true = cols 7..12)
//   samples  : (128,10)      fp32
// Output: scalar fp32 L_sim.
//
// R11 = R9 verbatim, with ONE isolated change: the PDL trigger moved from the
// end of second_kernel to right after the init __syncthreads(), so the tail
// grid launches (and does its samples prework) while the streamer runs.
// Correctness is carried by cudaGridDependencySynchronize() in final_kernel.

#define NPAIR 128
#define TE 1536                 // T*E
#define ROW_BYTES 6144          // TE * 4
#define NBUF 16                 // ring depth (2 buffers per consumer warp)

// smem layout (bytes, dynamic):
#define SM_W    0                       // w tile      (6144)
#define SM_Y    6144                    // y_pred_i[j] (6144)
#define SM_BUF  12288                   // 16 row buffers (98304)
#define SM_MBAR (12288 + 98304)         // full[16] @ +0, empty[16] @ +128
#define SMEM_TOTAL (SM_MBAR + 256)      // 110848

__device__ float g_second [NPAIR * NPAIR];
__device__ float g_secondT[NPAIR * NPAIR];

// ---- minimal PTX wrappers ---------------------------------------------------
__device__ __forceinline__ uint32_t smem_u32(const void* p) {
    return (uint32_t)__cvta_generic_to_shared(p);
}
__device__ __forceinline__ void mbar_init(uint32_t a, uint32_t cnt) {
    asm volatile("mbarrier.init.shared.b64 [%0], %1;" :: "r"(a), "r"(cnt) : "memory");
}
__device__ __forceinline__ void mbar_expect_tx(uint32_t a, uint32_t bytes) {
    asm volatile("mbarrier.arrive.expect_tx.shared.b64 _, [%0], %1;"
                 :: "r"(a), "r"(bytes) : "memory");
}
__device__ __forceinline__ void mbar_arrive(uint32_t a) {
    asm volatile("mbarrier.arrive.shared.b64 _, [%0];" :: "r"(a) : "memory");
}
__device__ __forceinline__ void mbar_wait(uint32_t a, uint32_t parity) {
    asm volatile(
        "{\n\t.reg .pred P;\n\t"
        "W_%=:\n\t"
        "mbarrier.try_wait.parity.acquire.cta.shared::cta.b64 P, [%0], %1, 0x989680;\n\t"
        "@P bra D_%=;\n\t"
        "bra W_%=;\n\t"
        "D_%=:\n\t}"
        :: "r"(a), "r"(parity) : "memory");
}
__device__ __forceinline__ void bulk_copy_g2s(uint32_t dst, const void* src,
                                              uint32_t bytes, uint32_t mbar) {
    asm volatile(
        "cp.async.bulk.shared::cluster.global.mbarrier::complete_tx::bytes "
        "[%0], [%1], %2, [%3];"
        :: "r"(dst), "l"(src), "r"(bytes), "r"(mbar) : "memory");
}

// ---------------------------------------------------------------------------
// Streaming kernel (bulk-async pipelined, R9-proven ~16.5 us).
// grid = (j:128, half:2) = 256 blocks (single wave @ 2 blocks/SM).
// block = 288 threads: warps 0-7 consume, warp 8 produces.
// Row r (0..63) -> i = half*64 + r; buffer b = r & 15; round k = r >> 4.
// ---------------------------------------------------------------------------
__global__ void __launch_bounds__(288)
second_kernel(const float* __restrict__ yij,
              const float* __restrict__ yi,
              const float* __restrict__ in1,
              float* __restrict__ out)
{
    extern __shared__ __align__(128) unsigned char smem[];
    float* w_f = reinterpret_cast<float*>(smem + SM_W);
    float* y_f = reinterpret_cast<float*>(smem + SM_Y);
    const uint32_t sbase      = smem_u32(smem);
    const uint32_t mbar_full  = sbase + SM_MBAR;         // + 8*b
    const uint32_t mbar_empty = sbase + SM_MBAR + 128;   // + 8*b

    const int j    = blockIdx.x;
    const int half = blockIdx.y;
    const int tid  = threadIdx.x;

    if (tid < NBUF) {
        mbar_init(mbar_full  + tid * 8, 1);
        mbar_init(mbar_empty + tid * 8, 1);
    }

    // Stage w[j,t,e] = (1/15360)/err^2 and y_pred_i[j].
    const float scale = 1.0f / 15360.0f;   // 1/(T*E*10)
    for (int idx = tid; idx < TE; idx += 288) {
        int t = idx / 6;
        int c = idx - t * 6;
        float e = in1[(j * 256 + t) * 15 + 7 + c];
        w_f[idx] = scale / (e * e);
        y_f[idx] = yi[j * TE + idx];
    }
    if (j == 0 && half == 0 && tid == 0) out[0] = 0.0f;
    __syncthreads();   // mbarriers + staging visible before pipeline starts

    // EARLY PDL trigger: all 256 blocks are wave-1 resident, so the tail grid
    // may launch ~1us into this kernel and overlap its launch + prework.
    // The tail's cudaGridDependencySynchronize() still waits for this grid's
    // full completion before reading g_second/g_secondT.
    cudaTriggerProgrammaticLaunchCompletion();

    const int warp = tid >> 5;
    const int lane = tid & 31;

    if (warp == 8) {
        // ---- producer: one elected lane issues 64 bulk copies ---------------
        if (lane == 0) {
            for (int r = 0; r < 64; ++r) {
                const int b = r & 15;
                const int k = r >> 4;
                if (k > 0) mbar_wait(mbar_empty + b * 8, (unsigned)((k - 1) & 1));
                mbar_expect_tx(mbar_full + b * 8, ROW_BYTES);
                const float* src =
                    yij + (size_t)((half * 64 + r) * NPAIR + j) * TE;
                bulk_copy_g2s(sbase + SM_BUF + b * ROW_BYTES, src,
                              ROW_BYTES, mbar_full + b * 8);
            }
        }
        return;
    }

    // ---- consumers: warp w owns buffers 2w, 2w+1 ----------------------------
    const int b0 = 2 * warp;
    const int b1 = 2 * warp + 1;
    const float4* w4   = reinterpret_cast<const float4*>(w_f);
    const float4* y4   = reinterpret_cast<const float4*>(y_f);
    const float4* buf0 = reinterpret_cast<const float4*>(smem + SM_BUF + b0 * ROW_BYTES);
    const float4* buf1 = reinterpret_cast<const float4*>(smem + SM_BUF + b1 * ROW_BYTES);

    for (int k = 0; k < 4; ++k) {
        mbar_wait(mbar_full + b0 * 8, (unsigned)(k & 1));
        mbar_wait(mbar_full + b1 * 8, (unsigned)(k & 1));

        float a0 = 0.0f, a1 = 0.0f;
        #pragma unroll
        for (int q = 0; q < 12; ++q) {
            const int x = lane + 32 * q;
            const float4 wv = w4[x];
            const float4 yv = y4[x];
            const float4 g0 = buf0[x];
            const float4 g1 = buf1[x];
            float d;
            d = g0.x - yv.x; a0 = fmaf(d * d, wv.x, a0);
            d = g0.y - yv.y; a0 = fmaf(d * d, wv.y, a0);
            d = g0.z - yv.z; a0 = fmaf(d * d, wv.z, a0);
            d = g0.w - yv.w; a0 = fmaf(d * d, wv.w, a0);
            d = g1.x - yv.x; a1 = fmaf(d * d, wv.x, a1);
            d = g1.y - yv.y; a1 = fmaf(d * d, wv.y, a1);
            d = g1.z - yv.z; a1 = fmaf(d * d, wv.z, a1);
            d = g1.w - yv.w; a1 = fmaf(d * d, wv.w, a1);
        }
        #pragma unroll
        for (int o = 16; o; o >>= 1) {
            a0 += __shfl_xor_sync(0xFFFFFFFFu, a0, o);
            a1 += __shfl_xor_sync(0xFFFFFFFFu, a1, o);
        }
        __syncwarp();          // all lanes done reading the buffers
        if (lane == 0) {
            const int i0 = half * 64 + k * 16 + 2 * warp;
            g_second [i0 * NPAIR + j]       = a0;
            g_second [(i0 + 1) * NPAIR + j] = a1;
            g_secondT[j * NPAIR + i0]       = a0;
            g_secondT[j * NPAIR + i0 + 1]   = a1;
            mbar_arrive(mbar_empty + b0 * 8);   // release buffers
            mbar_arrive(mbar_empty + b1 * 8);
        }
    }
}

// ---------------------------------------------------------------------------
// Tail kernel: verbatim R8/R9 (one (i,jj) pair per thread, PDL-overlapped).
// ---------------------------------------------------------------------------
__global__ void __launch_bounds__(256)
final_kernel(const float* __restrict__ samples,
             float* __restrict__ out)
{
    __shared__ float s_part[8];

    const int tid = threadIdx.x;
    const int jj  = tid & 127;
    const int i   = blockIdx.x * 2 + (tid >> 7);

    float S = 0.0f;
    #pragma unroll
    for (int d = 0; d < 10; ++d) {
        float df = __ldg(&samples[i * 10 + d]) - __ldg(&samples[jj * 10 + d]);
        S = fmaf(df, df, S);
    }

    cudaGridDependencySynchronize();

    float sA = g_second [i * NPAIR + jj];
    float sB = g_secondT[i * NPAIR + jj];
    float v  = fabsf(S * 0.1f - 0.5f * (sA + sB));

    #pragma unroll
    for (int o = 16; o; o >>= 1)
        v += __shfl_xor_sync(0xFFFFFFFFu, v, o);
    if ((tid & 31) == 0) s_part[tid >> 5] = v;
    __syncthreads();

    if (tid == 0) {
        float s = 0.0f;
        #pragma unroll
        for (int w = 0; w < 8; ++w) s += s_part[w];
        atomicAdd(out, s * (1.0f / 16384.0f));
    }
}

// ---------------------------------------------------------------------------
extern "C" void kernel_launch(void* const* d_in, const int* in_sizes, int n_in,
                              void* d_out, int out_size)
{
    (void)in_sizes; (void)n_in; (void)out_size;
    const float* yi      = (const float*)d_in[1];
    const float* yij     = (const float*)d_in[2];
    const float* in1     = (const float*)d_in[3];
    const float* samples = (const float*)d_in[4];
    float* out = (float*)d_out;

    static int smem_set = 0;
    if (!smem_set) {
        cudaFuncSetAttribute(second_kernel,
                             cudaFuncAttributeMaxDynamicSharedMemorySize,
                             SMEM_TOTAL);
        smem_set = 1;
    }

    dim3 grid1(NPAIR, 2);   // 256 blocks -> single wave at 2 blocks/SM
    second_kernel<<<grid1, 288, SMEM_TOTAL>>>(yij, yi, in1, out);

    cudaLaunchAttribute attrs[1];
    attrs[0].id = cudaLaunchAttributeProgrammaticStreamSerialization;
    attrs[0].val.programmaticStreamSerializationAllowed = 1;

    cudaLaunchConfig_t cfg = {};
    cfg.gridDim  = dim3(64, 1, 1);
    cfg.blockDim = dim3(256, 1, 1);
    cfg.dynamicSmemBytes = 0;
    cfg.stream   = 0;
    cfg.attrs    = attrs;
    cfg.numAttrs = 1;
    cudaLaunchKernelEx(&cfg, final_kernel, samples, out);
}

// round 12
// speedup vs baseline: 1.4954x; 1.1064x over previous
#include <cuda_runtime.h>
#include <cstdint>

// Shapes: N=128, T=256, E=6, D=10
//   y_pred_i : (128,256,6)   fp32
//   y_pred_ij: (128,128,256,6) fp32  (~100.7 MB, streamed once via cp.async.bulk)
//   input1   : (128,256,15)  fp32  (err_true = cols 7..12)
//   samples  : (128,10)      fp32
// Output: scalar fp32 L_sim.
//
// R12 = R9 verbatim + ONE instruction: the producer warp fires the PDL
// trigger after issuing its 64 bulk copies (~3-4us before block completion),
// so the tail grid's dispatch overlaps the streamer's final consumer round.
// Consumer code path is textually untouched.

#define NPAIR 128
#define TE 1536                 // T*E
#define ROW_BYTES 6144          // TE * 4
#define NBUF 16                 // ring depth (2 buffers per consumer warp)

// smem layout (bytes, dynamic):
#define SM_W    0                       // w tile      (6144)
#define SM_Y    6144                    // y_pred_i[j] (6144)
#define SM_BUF  12288                   // 16 row buffers (98304)
#define SM_MBAR (12288 + 98304)         // full[16] @ +0, empty[16] @ +128
#define SMEM_TOTAL (SM_MBAR + 256)      // 110848

__device__ float g_second [NPAIR * NPAIR];
__device__ float g_secondT[NPAIR * NPAIR];

// ---- minimal PTX wrappers ---------------------------------------------------
__device__ __forceinline__ uint32_t smem_u32(const void* p) {
    return (uint32_t)__cvta_generic_to_shared(p);
}
__device__ __forceinline__ void mbar_init(uint32_t a, uint32_t cnt) {
    asm volatile("mbarrier.init.shared.b64 [%0], %1;" :: "r"(a), "r"(cnt) : "memory");
}
__device__ __forceinline__ void mbar_expect_tx(uint32_t a, uint32_t bytes) {
    asm volatile("mbarrier.arrive.expect_tx.shared.b64 _, [%0], %1;"
                 :: "r"(a), "r"(bytes) : "memory");
}
__device__ __forceinline__ void mbar_arrive(uint32_t a) {
    asm volatile("mbarrier.arrive.shared.b64 _, [%0];" :: "r"(a) : "memory");
}
__device__ __forceinline__ void mbar_wait(uint32_t a, uint32_t parity) {
    asm volatile(
        "{\n\t.reg .pred P;\n\t"
        "W_%=:\n\t"
        "mbarrier.try_wait.parity.acquire.cta.shared::cta.b64 P, [%0], %1, 0x989680;\n\t"
        "@P bra D_%=;\n\t"
        "bra W_%=;\n\t"
        "D_%=:\n\t}"
        :: "r"(a), "r"(parity) : "memory");
}
__device__ __forceinline__ void bulk_copy_g2s(uint32_t dst, const void* src,
                                              uint32_t bytes, uint32_t mbar) {
    asm volatile(
        "cp.async.bulk.shared::cluster.global.mbarrier::complete_tx::bytes "
        "[%0], [%1], %2, [%3];"
        :: "r"(dst), "l"(src), "r"(bytes), "r"(mbar) : "memory");
}

// ---------------------------------------------------------------------------
// Streaming kernel (bulk-async pipelined, R9-proven).
// grid = (j:128, half:2) = 256 blocks (single wave @ 2 blocks/SM).
// block = 288 threads: warps 0-7 consume, warp 8 produces.
// Row r (0..63) -> i = half*64 + r; buffer b = r & 15; round k = r >> 4.
// ---------------------------------------------------------------------------
__global__ void __launch_bounds__(288)
second_kernel(const float* __restrict__ yij,
              const float* __restrict__ yi,
              const float* __restrict__ in1,
              float* __restrict__ out)
{
    extern __shared__ __align__(128) unsigned char smem[];
    float* w_f = reinterpret_cast<float*>(smem + SM_W);
    float* y_f = reinterpret_cast<float*>(smem + SM_Y);
    const uint32_t sbase      = smem_u32(smem);
    const uint32_t mbar_full  = sbase + SM_MBAR;         // + 8*b
    const uint32_t mbar_empty = sbase + SM_MBAR + 128;   // + 8*b

    const int j    = blockIdx.x;
    const int half = blockIdx.y;
    const int tid  = threadIdx.x;

    if (tid < NBUF) {
        mbar_init(mbar_full  + tid * 8, 1);
        mbar_init(mbar_empty + tid * 8, 1);
    }

    // Stage w[j,t,e] = (1/15360)/err^2 and y_pred_i[j].
    const float scale = 1.0f / 15360.0f;   // 1/(T*E*10)
    for (int idx = tid; idx < TE; idx += 288) {
        int t = idx / 6;
        int c = idx - t * 6;
        float e = in1[(j * 256 + t) * 15 + 7 + c];
        w_f[idx] = scale / (e * e);
        y_f[idx] = yi[j * TE + idx];
    }
    if (j == 0 && half == 0 && tid == 0) out[0] = 0.0f;
    __syncthreads();   // mbarriers + staging visible before pipeline starts

    const int warp = tid >> 5;
    const int lane = tid & 31;

    if (warp == 8) {
        // ---- producer: one elected lane issues 64 bulk copies ---------------
        if (lane == 0) {
            for (int r = 0; r < 64; ++r) {
                const int b = r & 15;
                const int k = r >> 4;
                if (k > 0) mbar_wait(mbar_empty + b * 8, (unsigned)((k - 1) & 1));
                mbar_expect_tx(mbar_full + b * 8, ROW_BYTES);
                const float* src =
                    yij + (size_t)((half * 64 + r) * NPAIR + j) * TE;
                bulk_copy_g2s(sbase + SM_BUF + b * ROW_BYTES, src,
                              ROW_BYTES, mbar_full + b * 8);
            }
        }
        // All copies issued: this block is ~1 consumer round from done.
        // Fire the PDL trigger so the tail grid's dispatch overlaps the drain.
        cudaTriggerProgrammaticLaunchCompletion();
        return;
    }

    // ---- consumers: warp w owns buffers 2w, 2w+1 ----------------------------
    const int b0 = 2 * warp;
    const int b1 = 2 * warp + 1;
    const float4* w4   = reinterpret_cast<const float4*>(w_f);
    const float4* y4   = reinterpret_cast<const float4*>(y_f);
    const float4* buf0 = reinterpret_cast<const float4*>(smem + SM_BUF + b0 * ROW_BYTES);
    const float4* buf1 = reinterpret_cast<const float4*>(smem + SM_BUF + b1 * ROW_BYTES);

    for (int k = 0; k < 4; ++k) {
        mbar_wait(mbar_full + b0 * 8, (unsigned)(k & 1));
        mbar_wait(mbar_full + b1 * 8, (unsigned)(k & 1));

        float a0 = 0.0f, a1 = 0.0f;
        #pragma unroll
        for (int q = 0; q < 12; ++q) {
            const int x = lane + 32 * q;
            const float4 wv = w4[x];
            const float4 yv = y4[x];
            const float4 g0 = buf0[x];
            const float4 g1 = buf1[x];
            float d;
            d = g0.x - yv.x; a0 = fmaf(d * d, wv.x, a0);
            d = g0.y - yv.y; a0 = fmaf(d * d, wv.y, a0);
            d = g0.z - yv.z; a0 = fmaf(d * d, wv.z, a0);
            d = g0.w - yv.w; a0 = fmaf(d * d, wv.w, a0);
            d = g1.x - yv.x; a1 = fmaf(d * d, wv.x, a1);
            d = g1.y - yv.y; a1 = fmaf(d * d, wv.y, a1);
            d = g1.z - yv.z; a1 = fmaf(d * d, wv.z, a1);
            d = g1.w - yv.w; a1 = fmaf(d * d, wv.w, a1);
        }
        #pragma unroll
        for (int o = 16; o; o >>= 1) {
            a0 += __shfl_xor_sync(0xFFFFFFFFu, a0, o);
            a1 += __shfl_xor_sync(0xFFFFFFFFu, a1, o);
        }
        __syncwarp();          // all lanes done reading the buffers
        if (lane == 0) {
            const int i0 = half * 64 + k * 16 + 2 * warp;
            g_second [i0 * NPAIR + j]       = a0;
            g_second [(i0 + 1) * NPAIR + j] = a1;
            g_secondT[j * NPAIR + i0]       = a0;
            g_secondT[j * NPAIR + i0 + 1]   = a1;
            mbar_arrive(mbar_empty + b0 * 8);   // release buffers
            mbar_arrive(mbar_empty + b1 * 8);
        }
    }
}

// ---------------------------------------------------------------------------
// Tail kernel: verbatim R8/R9 (one (i,jj) pair per thread, PDL-overlapped).
// ---------------------------------------------------------------------------
__global__ void __launch_bounds__(256)
final_kernel(const float* __restrict__ samples,
             float* __restrict__ out)
{
    __shared__ float s_part[8];

    const int tid = threadIdx.x;
    const int jj  = tid & 127;
    const int i   = blockIdx.x * 2 + (tid >> 7);

    float S = 0.0f;
    #pragma unroll
    for (int d = 0; d < 10; ++d) {
        float df = __ldg(&samples[i * 10 + d]) - __ldg(&samples[jj * 10 + d]);
        S = fmaf(df, df, S);
    }

    cudaGridDependencySynchronize();

    float sA = g_second [i * NPAIR + jj];
    float sB = g_secondT[i * NPAIR + jj];
    float v  = fabsf(S * 0.1f - 0.5f * (sA + sB));

    #pragma unroll
    for (int o = 16; o; o >>= 1)
        v += __shfl_xor_sync(0xFFFFFFFFu, v, o);
    if ((tid & 31) == 0) s_part[tid >> 5] = v;
    __syncthreads();

    if (tid == 0) {
        float s = 0.0f;
        #pragma unroll
        for (int w = 0; w < 8; ++w) s += s_part[w];
        atomicAdd(out, s * (1.0f / 16384.0f));
    }
}

// ---------------------------------------------------------------------------
extern "C" void kernel_launch(void* const* d_in, const int* in_sizes, int n_in,
                              void* d_out, int out_size)
{
    (void)in_sizes; (void)n_in; (void)out_size;
    const float* yi      = (const float*)d_in[1];
    const float* yij     = (const float*)d_in[2];
    const float* in1     = (const float*)d_in[3];
    const float* samples = (const float*)d_in[4];
    float* out = (float*)d_out;

    static int smem_set = 0;
    if (!smem_set) {
        cudaFuncSetAttribute(second_kernel,
                             cudaFuncAttributeMaxDynamicSharedMemorySize,
                             SMEM_TOTAL);
        smem_set = 1;
    }

    dim3 grid1(NPAIR, 2);   // 256 blocks -> single wave at 2 blocks/SM
    second_kernel<<<grid1, 288, SMEM_TOTAL>>>(yij, yi, in1, out);

    cudaLaunchAttribute attrs[1];
    attrs[0].id = cudaLaunchAttributeProgrammaticStreamSerialization;
    attrs[0].val.programmaticStreamSerializationAllowed = 1;

    cudaLaunchConfig_t cfg = {};
    cfg.gridDim  = dim3(64, 1, 1);
    cfg.blockDim = dim3(256, 1, 1);
    cfg.dynamicSmemBytes = 0;
    cfg.stream   = 0;
    cfg.attrs    = attrs;
    cfg.numAttrs = 1;
    cudaLaunchKernelEx(&cfg, final_kernel, samples, out);
}